// round 2
// baseline (speedup 1.0000x reference)
#include <cuda_runtime.h>
#include <cuda_bf16.h>
#include <cmath>

// SimpleHashEncoder1D: out[p, l*2 + f] = hash_table[floor((x[p]+1)/2 * scale_l + 0.5) % T, f]
//
// Numerics (must bit-match jax f32 chain):
//   b = exp((log(2^19)-log(2^4))/15) in f32  ==  1.99999988079071 (1 ulp BELOW 2.0f),
//       inferred from round-1 rel_err=0.2295 matching the flip model for e=-5.96e-8.
//   scale_l = f32(16 * f32(b^l)) - 1.0f   (16*pf exact; b^l correctly rounded via double pow)
//   x_scaled = xn*scale + 0.5 with SEPARATE roundings (no FMA) to match XLA elementwise ops.

#define T_SIZE   524288      // 2^19
#define N_POINTS (1 << 21)   // 2097152
#define NUM_L    16

struct Scales { float s[NUM_L]; };

__global__ __launch_bounds__(256)
void hashenc_kernel(const float* __restrict__ x,
                    const float2* __restrict__ table,
                    float4* __restrict__ out,
                    const Scales sc)
{
    int gid = blockIdx.x * blockDim.x + threadIdx.x;   // 16M threads total
    int p = gid >> 3;          // point index
    int j = gid & 7;           // level-pair index 0..7

    float xv = __ldg(&x[p]);
    // xn = (x + 1) / 2 : add rounds, then exact *0.5
    float xn = __fmul_rn(__fadd_rn(xv, 1.0f), 0.5f);

    int l0 = j << 1;
    float s0 = sc.s[l0];
    float s1 = sc.s[l0 + 1];

    // v = xn*s + 0.5 with separate roundings (no FMA contraction)
    float v0 = __fadd_rn(__fmul_rn(xn, s0), 0.5f);
    float v1 = __fadd_rn(__fmul_rn(xn, s1), 0.5f);

    // v >= 0.5 always -> (int) truncation == floor; indices < T
    int i0 = ((int)v0) & (T_SIZE - 1);
    int i1 = ((int)v1) & (T_SIZE - 1);

    float2 f0 = __ldg(&table[i0]);
    float2 f1 = __ldg(&table[i1]);

    out[gid] = make_float4(f0.x, f0.y, f1.x, f1.y);
}

extern "C" void kernel_launch(void* const* d_in, const int* in_sizes, int n_in,
                              void* d_out, int out_size)
{
    const float*  x     = (const float*)d_in[0];
    const float2* table = (const float2*)d_in[1];
    // d_in[2] is `bound` (== 1): folded into the normalize.
    float4* out = (float4*)d_out;

    // b = f32 value 1 ulp below 2.0f (0x3FFFFFFF)
    const float b = 1.99999988079071044921875f;
    Scales sc;
    for (int l = 0; l < NUM_L; l++) {
        double p  = pow((double)b, (double)l);   // correctly rounded in double
        float  pf = (float)p;                    // round-to-nearest f32 == f32 pow result
        float  q  = 16.0f * pf;                  // exact (power-of-two multiply)
        sc.s[l]   = q - 1.0f;                    // f32 rounding
    }

    int total_threads = N_POINTS * (NUM_L / 2);  // 16M
    int block = 256;
    int grid  = total_threads / block;           // 65536
    hashenc_kernel<<<grid, block>>>(x, table, out, sc);
}

// round 3
// speedup vs baseline: 1.6250x; 1.6250x over previous
#include <cuda_runtime.h>
#include <cuda_bf16.h>
#include <cmath>

// SimpleHashEncoder1D: out[p, l*2 + f] = hash_table[floor((x[p]+1)/2 * scale_l + 0.5) % T, f]
//
// Numerics (LOCKED, rel_err=0.0 in R2 — do not change):
//   b = f32 1 ulp below 2.0f; scale_l = f32(16 * f32(b^l)) - 1.0f via double pow;
//   x_scaled = xn*scale + 0.5 with SEPARATE roundings (no FMA).
//
// R3 perf change: 4 points per thread (same level-pair j) to batch 8 independent
// gathers per thread -> 4x per-warp MLP against L1tex queue latency.
// Stores remain 4 perfectly-coalesced float4 streams.

#define T_SIZE   524288      // 2^19
#define N_POINTS (1 << 21)   // 2097152
#define NUM_L    16
#define PTS_PER_THREAD 4
#define P_QUARTER (N_POINTS / PTS_PER_THREAD)   // 524288

struct Scales { float s[NUM_L]; };

__global__ __launch_bounds__(256)
void hashenc_kernel(const float* __restrict__ x,
                    const float2* __restrict__ table,
                    float4* __restrict__ out,
                    const Scales sc)
{
    int gid = blockIdx.x * blockDim.x + threadIdx.x;   // 4M threads
    int j  = gid & 7;          // level-pair index 0..7
    int p0 = gid >> 3;         // base point in [0, 512K)

    int l0 = j << 1;
    float s0 = sc.s[l0];
    float s1 = sc.s[l0 + 1];

    // Batch the 4 x-loads (independent)
    float xv[PTS_PER_THREAD];
#pragma unroll
    for (int k = 0; k < PTS_PER_THREAD; k++)
        xv[k] = __ldg(&x[p0 + k * P_QUARTER]);

    // Compute all 8 indices (ALU only, keeps loads hoistable)
    int i0[PTS_PER_THREAD], i1[PTS_PER_THREAD];
#pragma unroll
    for (int k = 0; k < PTS_PER_THREAD; k++) {
        float xn = __fmul_rn(__fadd_rn(xv[k], 1.0f), 0.5f);
        float v0 = __fadd_rn(__fmul_rn(xn, s0), 0.5f);
        float v1 = __fadd_rn(__fmul_rn(xn, s1), 0.5f);
        i0[k] = ((int)v0) & (T_SIZE - 1);   // v >= 0.5 -> trunc == floor
        i1[k] = ((int)v1) & (T_SIZE - 1);
    }

    // Batch all 8 gathers (independent -> 8 outstanding LDG.64 per thread)
    float2 f0[PTS_PER_THREAD], f1[PTS_PER_THREAD];
#pragma unroll
    for (int k = 0; k < PTS_PER_THREAD; k++) {
        f0[k] = __ldg(&table[i0[k]]);
        f1[k] = __ldg(&table[i1[k]]);
    }

    // 4 coalesced float4 store streams: out index = point*8 + j
#pragma unroll
    for (int k = 0; k < PTS_PER_THREAD; k++) {
        int oi = ((p0 + k * P_QUARTER) << 3) + j;
        out[oi] = make_float4(f0[k].x, f0[k].y, f1[k].x, f1[k].y);
    }
}

extern "C" void kernel_launch(void* const* d_in, const int* in_sizes, int n_in,
                              void* d_out, int out_size)
{
    const float*  x     = (const float*)d_in[0];
    const float2* table = (const float2*)d_in[1];
    // d_in[2] is `bound` (== 1): folded into the normalize.
    float4* out = (float4*)d_out;

    // b = f32 value 1 ulp below 2.0f (0x3FFFFFFF)
    const float b = 1.99999988079071044921875f;
    Scales sc;
    for (int l = 0; l < NUM_L; l++) {
        double pd = pow((double)b, (double)l);   // correctly rounded double
        float  pf = (float)pd;                   // == f32 pow result
        float  q  = 16.0f * pf;                  // exact
        sc.s[l]   = q - 1.0f;                    // f32 rounding
    }

    int total_threads = (N_POINTS / PTS_PER_THREAD) * (NUM_L / 2);  // 4M
    int block = 256;
    int grid  = total_threads / block;                              // 16384
    hashenc_kernel<<<grid, block>>>(x, table, out, sc);
}